// round 12
// baseline (speedup 1.0000x reference)
#include <cuda_runtime.h>
#include <cuda_bf16.h>
#include <cstdint>

// Per-batch 21x21 cross-correlation, reflect padding 10.
// input: (16,3,768,768) f32   kernel: (16,21,21) f32   out: (16,3,768,768) f32
// FFMA2 (fma.rn.f32x2), lanes = two adjacent OUTPUT ROWS (R7 core).
// R12: persistent CTAs (296 = 2/SM), 11-12 tiles each in bz-contiguous order,
//      cross-tile double-buffered cp.async halo prefetch, qtab rebuilt only on
//      batch change.

#define BB 16
#define CC 3
#define HH 768
#define WW 768
#define KK 21
#define PP 10

#define TH 64            // output rows per tile (4 per thread: 16 ty groups)
#define TW 128           // output cols per tile (8 per thread: 16 tx groups)
#define IH (TH + KK - 1) // 84 input rows in tile
#define IW (TW + KK - 1) // 148 input cols needed
#define SW 152           // smem tile row stride (floats), 16B aligned
#define QJ 24            // quads per table row (21 real + pad)

#define TILE_FLOATS (IH * SW)                 // 12768 (51072 B)
#define QUAD_COUNT  (24 * QJ)                 // 576 quads (16B each)
#define SMEM_BYTES  (2 * TILE_FLOATS * 4 + QUAD_COUNT * 16)   // 111360

#define NTILES   3456     // 6 bx * 12 by * 48 bz
#define TPI      72       // tiles per image-channel group (bz): 6*12
#define NCTAS    296      // 2 per SM * 148

__device__ __forceinline__ int reflect_idx(int t) {
    if (t < 0) return -t;
    if (t >= HH) return 2 * HH - 2 - t;
    return t;
}

__device__ __forceinline__ void ffma2(double& d, double a, double b) {
    asm("fma.rn.f32x2 %0, %1, %2, %0;"
        : "+d"(d) : "l"(__double_as_longlong(a)), "l"(__double_as_longlong(b)));
}

__device__ __forceinline__ double bcast(float x) {
    double r;
    asm("mov.b64 %0, {%1, %1};" : "=d"(r) : "f"(x));
    return r;
}

__device__ __forceinline__ void unpack2(float& lo, float& hi, double p) {
    asm("mov.b64 {%0, %1}, %2;" : "=f"(lo), "=f"(hi) : "d"(p));
}

__device__ __forceinline__ void cp_async4(uint32_t dst_smem, const float* src) {
    asm volatile("cp.async.ca.shared.global [%0], [%1], 4;"
                 :: "r"(dst_smem), "l"(src));
}

__global__ __launch_bounds__(256, 2)
void blur_kernel(const float* __restrict__ in,
                 const float* __restrict__ ker,
                 float* __restrict__ out)
{
    extern __shared__ float smem[];
    float* qtab = smem + 2 * TILE_FLOATS;     // 24 x QJ quads (float4)

    const int tid  = threadIdx.x;
    const int lane = tid & 31;
    const int wrp  = tid >> 5;                // 0..7

    const uint32_t smem_base = (uint32_t)__cvta_generic_to_shared(smem);
    const uint32_t kern_base = (uint32_t)__cvta_generic_to_shared(qtab);

    // persistent chunking: CTAs 0..199 -> 12 tiles, 200..295 -> 11 tiles
    const int c     = blockIdx.x;
    const int start = c * 11 + (c < 200 ? c : 200);
    const int nt    = 11 + (c < 200 ? 1 : 0);
    const int end   = start + nt;

    // ---- issue cp.async halo load of tile `t` into buffer p ----
    #define LOAD_TILE(t, p) do {                                              \
        const int bz_ = (t) / TPI;                                            \
        const int rm_ = (t) - bz_ * TPI;                                      \
        const int by_ = rm_ / 6;                                              \
        const int bx_ = rm_ - by_ * 6;                                        \
        const int gh0_ = by_ * TH - PP;                                       \
        const int gw0_ = bx_ * TW - PP;                                       \
        const float* img_ = in + (long)bz_ * (HH * WW);                       \
        const uint32_t tb_ = smem_base + (uint32_t)((p) * TILE_FLOATS * 4);   \
        _Pragma("unroll 1")                                                   \
        for (int r_ = wrp; r_ < IH; r_ += 8) {                                \
            const float* src_ = img_ + (long)reflect_idx(gh0_ + r_) * WW;     \
            uint32_t dst_ = tb_ + (uint32_t)(r_ * SW * 4);                    \
            _Pragma("unroll")                                                 \
            for (int c5_ = 0; c5_ < 5; ++c5_) {                               \
                int cc_ = c5_ * 32 + lane;                                    \
                if (cc_ < IW)                                                 \
                    cp_async4(dst_ + cc_ * 4, src_ + reflect_idx(gw0_ + cc_));\
            }                                                                 \
        }                                                                     \
    } while (0)

    // ---- build weight QUAD table for batch b ----
    // quad[t][j] = (w[t][j], w[t-1][j], w[t-2][j], w[t-3][j]), zeros outside
    #define BUILD_QTAB(bb) do {                                               \
        const float* kb_ = ker + (bb) * (KK * KK);                            \
        float4* q4_ = (float4*)qtab;                                          \
        _Pragma("unroll 1")                                                   \
        for (int idx_ = tid; idx_ < QUAD_COUNT; idx_ += 256) {                \
            int t_ = idx_ / QJ;                                               \
            int j_ = idx_ - t_ * QJ;                                          \
            float v0_ = 0.f, v1_ = 0.f, v2_ = 0.f, v3_ = 0.f;                 \
            if (j_ < KK) {                                                    \
                if (t_ <= 20)                v0_ = kb_[t_ * KK + j_];         \
                if (t_ >= 1 && t_ - 1 <= 20) v1_ = kb_[(t_ - 1) * KK + j_];   \
                if (t_ >= 2 && t_ - 2 <= 20) v2_ = kb_[(t_ - 2) * KK + j_];   \
                if (t_ >= 3 && t_ - 3 <= 20) v3_ = kb_[(t_ - 3) * KK + j_];   \
            }                                                                 \
            q4_[idx_] = make_float4(v0_, v1_, v2_, v3_);                      \
        }                                                                     \
    } while (0)

    // prologue: load first tile + its weight table
    int bcur = (start / TPI) / CC;
    LOAD_TILE(start, 0);
    BUILD_QTAB(bcur);
    asm volatile("cp.async.commit_group;" ::: "memory");
    asm volatile("cp.async.wait_group 0;" ::: "memory");
    __syncthreads();

    const int tx = tid & 15;     // 0..15 -> 8-wide column group
    const int ty = tid >> 4;     // 0..15 -> 4-row group
    const int wc = tx * 8;       // local col of first output
    const int rb = ty * 4;       // first output row of this thread

    #pragma unroll 1
    for (int t = start; t < end; ++t) {
        const int p = (t - start) & 1;

        // prefetch next tile into the other buffer
        if (t + 1 < end) {
            LOAD_TILE(t + 1, 1 - p);
        }
        asm volatile("cp.async.commit_group;" ::: "memory");

        // ---- compute tile t from buffer p ----
        const int bz = t / TPI;
        const int rm = t - bz * TPI;
        const int by = rm / 6;
        const int bx = rm - by * 6;

        const float* tile = smem + p * TILE_FLOATS;

        double pcA[8], pcB[8];
        #pragma unroll
        for (int cc = 0; cc < 8; ++cc) { pcA[cc] = 0.0; pcB[cc] = 0.0; }

        double xb[28];

        #define LOADROW(r) do {                                               \
            const float* rp_ = &tile[(rb + (r)) * SW + wc];                   \
            _Pragma("unroll")                                                 \
            for (int v = 0; v < 7; ++v) {                                     \
                float4 q_ = *reinterpret_cast<const float4*>(rp_ + 4 * v);    \
                xb[4*v+0] = bcast(q_.x); xb[4*v+1] = bcast(q_.y);             \
                xb[4*v+2] = bcast(q_.z); xb[4*v+3] = bcast(q_.w);             \
            }                                                                 \
        } while (0)

        #define ACC2Q(r) do {                                                 \
            const uint32_t qa_ = kern_base + (uint32_t)((r) * (QJ * 16));     \
            _Pragma("unroll")                                                 \
            for (int j = 0; j < KK; ++j) {                                    \
                unsigned long long la_, lb_;                                  \
                asm volatile("ld.shared.v2.u64 {%0, %1}, [%2];"               \
                             : "=l"(la_), "=l"(lb_) : "r"(qa_ + j * 16));     \
                const double wA_ = __longlong_as_double(la_);                 \
                const double wB_ = __longlong_as_double(lb_);                 \
                _Pragma("unroll")                                             \
                for (int cc = 0; cc < 8; ++cc) {                              \
                    ffma2(pcA[cc], xb[j + cc], wA_);                          \
                    ffma2(pcB[cc], xb[j + cc], wB_);                          \
                }                                                             \
            }                                                                 \
        } while (0)

        #define ACC1P(PC, r, off) do {                                        \
            const uint32_t qa_ = kern_base                                    \
                + (uint32_t)((r) * (QJ * 16) + (off));                        \
            _Pragma("unroll")                                                 \
            for (int j = 0; j < KK; ++j) {                                    \
                unsigned long long l_;                                        \
                asm volatile("ld.shared.b64 %0, [%1];"                        \
                             : "=l"(l_) : "r"(qa_ + j * 16));                 \
                const double w_ = __longlong_as_double(l_);                   \
                _Pragma("unroll")                                             \
                for (int cc = 0; cc < 8; ++cc) ffma2(PC[cc], xb[j + cc], w_); \
            }                                                                 \
        } while (0)

        LOADROW(0); ACC1P(pcA, 0, 0);
        LOADROW(1); ACC1P(pcA, 1, 0);

        #pragma unroll 1
        for (int r = 2; r <= 21; ++r) {
            LOADROW(r);
            ACC2Q(r);
        }

        LOADROW(22); ACC1P(pcB, 22, 8);
        LOADROW(23); ACC1P(pcB, 23, 8);

        // ---- write 4 x 8 outputs ----
        const int oh = by * TH + rb;
        const int ow = bx * TW + wc;
        float* op = out + (long)bz * (HH * WW) + (long)oh * WW + ow;

        float r0[8], r1[8], r2[8], r3[8];
        #pragma unroll
        for (int cc = 0; cc < 8; ++cc) {
            unpack2(r0[cc], r1[cc], pcA[cc]);
            unpack2(r2[cc], r3[cc], pcB[cc]);
        }
        #pragma unroll
        for (int v = 0; v < 2; ++v) {
            *reinterpret_cast<float4*>(op + 0*WW + 4*v) = make_float4(r0[4*v], r0[4*v+1], r0[4*v+2], r0[4*v+3]);
            *reinterpret_cast<float4*>(op + 1*WW + 4*v) = make_float4(r1[4*v], r1[4*v+1], r1[4*v+2], r1[4*v+3]);
            *reinterpret_cast<float4*>(op + 2*WW + 4*v) = make_float4(r2[4*v], r2[4*v+1], r2[4*v+2], r2[4*v+3]);
            *reinterpret_cast<float4*>(op + 3*WW + 4*v) = make_float4(r3[4*v], r3[4*v+1], r3[4*v+2], r3[4*v+3]);
        }

        #undef LOADROW
        #undef ACC2Q
        #undef ACC1P

        // wait for next tile's prefetch; then rebuild qtab if batch changes
        asm volatile("cp.async.wait_group 0;" ::: "memory");
        __syncthreads();
        if (t + 1 < end) {
            const int bn = ((t + 1) / TPI) / CC;
            if (bn != bcur) {
                BUILD_QTAB(bn);
                bcur = bn;
                __syncthreads();
            }
        }
    }

    #undef LOAD_TILE
    #undef BUILD_QTAB
}

extern "C" void kernel_launch(void* const* d_in, const int* in_sizes, int n_in,
                              void* d_out, int out_size)
{
    const float* in  = (const float*)d_in[0];   // (16,3,768,768)
    const float* ker = (const float*)d_in[1];   // (16,21,21)
    float* out = (float*)d_out;

    cudaFuncSetAttribute(blur_kernel,
                         cudaFuncAttributeMaxDynamicSharedMemorySize, SMEM_BYTES);

    blur_kernel<<<NCTAS, 256, SMEM_BYTES>>>(in, ker, out);
}

// round 13
// speedup vs baseline: 1.0154x; 1.0154x over previous
#include <cuda_runtime.h>
#include <cuda_bf16.h>
#include <cstdint>

// Per-batch 21x21 cross-correlation, reflect padding 10.
// input: (16,3,768,768) f32   kernel: (16,21,21) f32   out: (16,3,768,768) f32
// FFMA2 (fma.rn.f32x2), lanes = two adjacent OUTPUT ROWS (R7 core math).
// R13: conflict-free chunked tile layout. Row = 18 chunks x 12 floats (48B
//      stride, cols 8q..8q+11, 1.5x redundant). Lane window stride 48B ->
//      per-phase banks 12l mod 32 all distinct -> LDS.128 conflict-free with
//      zero extra compute instructions. TH=48, block 192, 3 CTAs/SM.

#define BB 16
#define CC 3
#define HH 768
#define WW 768
#define KK 21
#define PP 10

#define TH 48            // output rows per CTA (4 per thread: 12 ty groups)
#define TW 128           // output cols per CTA (8 per thread: 16 tx groups)
#define IH (TH + KK - 1) // 68 input rows in tile
#define IW (TW + KK - 1) // 148 input cols needed
#define NCHUNK 18        // chunks per row: chunk q = cols 8q..8q+11
#define SW (NCHUNK * 12) // 216 floats per tile row
#define QJ 24            // quads per table row (21 real + pad)
#define NTHREADS 192

#define TILE_FLOATS (IH * SW)                 // 14688 (58752 B)
#define QUAD_COUNT  (24 * QJ)                 // 576 quads (16B each)
#define SMEM_BYTES  (TILE_FLOATS * 4 + QUAD_COUNT * 16)   // 67968

__device__ __forceinline__ int reflect_idx(int t) {
    if (t < 0) return -t;
    if (t >= HH) return 2 * HH - 2 - t;
    return t;
}

// d.lo += a.lo*b.lo ; d.hi += a.hi*b.hi   (one SASS FFMA2)
__device__ __forceinline__ void ffma2(double& d, double a, double b) {
    asm("fma.rn.f32x2 %0, %1, %2, %0;"
        : "+d"(d) : "l"(__double_as_longlong(a)), "l"(__double_as_longlong(b)));
}

// broadcast float into both lanes of a 64b pair
__device__ __forceinline__ double bcast(float x) {
    double r;
    asm("mov.b64 %0, {%1, %1};" : "=d"(r) : "f"(x));
    return r;
}

__device__ __forceinline__ void unpack2(float& lo, float& hi, double p) {
    asm("mov.b64 {%0, %1}, %2;" : "=f"(lo), "=f"(hi) : "d"(p));
}

__device__ __forceinline__ void cp_async4(uint32_t dst_smem, const float* src) {
    asm volatile("cp.async.ca.shared.global [%0], [%1], 4;"
                 :: "r"(dst_smem), "l"(src));
}

__global__ __launch_bounds__(NTHREADS, 3)
void blur_kernel(const float* __restrict__ in,
                 const float* __restrict__ ker,
                 float* __restrict__ out)
{
    extern __shared__ float smem[];
    float* tile = smem;                                    // IH x SW floats
    float* qtab = smem + TILE_FLOATS;                      // 24 x QJ quads

    const int tid  = threadIdx.x;
    const int lane = tid & 31;
    const int wrp  = tid >> 5;             // 0..5
    const int bx = blockIdx.x;             // 0..5   W tiles
    const int by = blockIdx.y;             // 0..15  H tiles
    const int bz = blockIdx.z;             // 0..47  b*3+c
    const int b  = bz / CC;

    const uint32_t tile_base = (uint32_t)__cvta_generic_to_shared(tile);
    const uint32_t kern_base = (uint32_t)__cvta_generic_to_shared(qtab);

    // ---- input halo tile via cp.async, chunked layout ----
    // float idx in row: chunk q = idx/12, off = idx%12 -> col 8q+off
    {
        const int gh0 = by * TH - PP;
        const int gw0 = bx * TW - PP;
        const float* img = in + (long)bz * (HH * WW);
        #pragma unroll 1
        for (int r = wrp; r < IH; r += 6) {
            const float* src = img + (long)reflect_idx(gh0 + r) * WW;
            uint32_t dst = tile_base + (uint32_t)(r * SW * 4);
            #pragma unroll
            for (int c7 = 0; c7 < 7; ++c7) {
                int idx = c7 * 32 + lane;            // 0..223
                if (idx < SW) {
                    int q   = idx / 12;
                    int off = idx - q * 12;
                    int col = q * 8 + off;           // 0..147
                    cp_async4(dst + idx * 4, src + reflect_idx(gw0 + col));
                }
            }
        }
    }

    // ---- build weight QUAD table while cp.async is in flight ----
    // quad[t][j] = (w[t][j], w[t-1][j], w[t-2][j], w[t-3][j]), zeros outside [0,20]
    {
        const float* kb = ker + b * (KK * KK);
        float4* q4 = (float4*)qtab;
        #pragma unroll 1
        for (int idx = tid; idx < QUAD_COUNT; idx += NTHREADS) {
            int t = idx / QJ;
            int j = idx - t * QJ;
            float v0 = 0.f, v1 = 0.f, v2 = 0.f, v3 = 0.f;
            if (j < KK) {
                if (t     <= 20)           v0 = kb[t * KK + j];
                if (t >= 1 && t - 1 <= 20) v1 = kb[(t - 1) * KK + j];
                if (t >= 2 && t - 2 <= 20) v2 = kb[(t - 2) * KK + j];
                if (t >= 3 && t - 3 <= 20) v3 = kb[(t - 3) * KK + j];
            }
            q4[idx] = make_float4(v0, v1, v2, v3);
        }
    }

    asm volatile("cp.async.commit_group;" ::: "memory");
    asm volatile("cp.async.wait_group 0;" ::: "memory");
    __syncthreads();

    const int tx = tid & 15;     // 0..15 -> 8-wide column group
    const int ty = tid >> 4;     // 0..11 -> 4-row group
    const int wc = tx * 8;       // first output col of this thread
    const int rb = ty * 4;       // first output row of this thread

    // accumulators: pcA lanes = (row rb, rb+1), pcB lanes = (row rb+2, rb+3)
    double pcA[8], pcB[8];
    #pragma unroll
    for (int c = 0; c < 8; ++c) { pcA[c] = 0.0; pcB[c] = 0.0; }

    double xb[28];   // broadcast pairs of the 28-float window

    // window of thread tx at row: floats tx*12 + {0..11, 16..23, 28..35}
    // 7 LDS.128 at byte offsets {0,16,32,64,80,112,128}; lane stride 48B ->
    // conflict-free. xb[c]: c 0-11 <- q0..q2, c 12-19 <- q3..q4, c 20-27 <- q5..q6
    #define LOADROW(r) do {                                                   \
        const float* rp_ = &tile[(rb + (r)) * SW + tx * 12];                  \
        float4 q0_ = *reinterpret_cast<const float4*>(rp_ + 0);               \
        float4 q1_ = *reinterpret_cast<const float4*>(rp_ + 4);               \
        float4 q2_ = *reinterpret_cast<const float4*>(rp_ + 8);               \
        float4 q3_ = *reinterpret_cast<const float4*>(rp_ + 16);              \
        float4 q4_ = *reinterpret_cast<const float4*>(rp_ + 20);              \
        float4 q5_ = *reinterpret_cast<const float4*>(rp_ + 28);              \
        float4 q6_ = *reinterpret_cast<const float4*>(rp_ + 32);              \
        xb[0]=bcast(q0_.x);  xb[1]=bcast(q0_.y);  xb[2]=bcast(q0_.z);  xb[3]=bcast(q0_.w);  \
        xb[4]=bcast(q1_.x);  xb[5]=bcast(q1_.y);  xb[6]=bcast(q1_.z);  xb[7]=bcast(q1_.w);  \
        xb[8]=bcast(q2_.x);  xb[9]=bcast(q2_.y);  xb[10]=bcast(q2_.z); xb[11]=bcast(q2_.w); \
        xb[12]=bcast(q3_.x); xb[13]=bcast(q3_.y); xb[14]=bcast(q3_.z); xb[15]=bcast(q3_.w); \
        xb[16]=bcast(q4_.x); xb[17]=bcast(q4_.y); xb[18]=bcast(q4_.z); xb[19]=bcast(q4_.w); \
        xb[20]=bcast(q5_.x); xb[21]=bcast(q5_.y); xb[22]=bcast(q5_.z); xb[23]=bcast(q5_.w); \
        xb[24]=bcast(q6_.x); xb[25]=bcast(q6_.y); xb[26]=bcast(q6_.z); xb[27]=bcast(q6_.w); \
    } while (0)

    // both acc sets, one LDS.128 per j: lo pair -> pcA, hi pair -> pcB
    #define ACC2Q(r) do {                                                     \
        const uint32_t qa_ = kern_base + (uint32_t)((r) * (QJ * 16));         \
        _Pragma("unroll")                                                     \
        for (int j = 0; j < KK; ++j) {                                        \
            unsigned long long la_, lb_;                                      \
            asm volatile("ld.shared.v2.u64 {%0, %1}, [%2];"                   \
                         : "=l"(la_), "=l"(lb_) : "r"(qa_ + j * 16));         \
            const double wA_ = __longlong_as_double(la_);                     \
            const double wB_ = __longlong_as_double(lb_);                     \
            _Pragma("unroll")                                                 \
            for (int c = 0; c < 8; ++c) {                                     \
                ffma2(pcA[c], xb[j + c], wA_);                                \
                ffma2(pcB[c], xb[j + c], wB_);                                \
            }                                                                 \
        }                                                                     \
    } while (0)

    // single acc set; off = 0 -> lo pair (pcA), off = 8 -> hi pair (pcB)
    #define ACC1P(PC, r, off) do {                                            \
        const uint32_t qa_ = kern_base + (uint32_t)((r) * (QJ * 16) + (off)); \
        _Pragma("unroll")                                                     \
        for (int j = 0; j < KK; ++j) {                                        \
            unsigned long long l_;                                            \
            asm volatile("ld.shared.b64 %0, [%1];"                            \
                         : "=l"(l_) : "r"(qa_ + j * 16));                     \
            const double w_ = __longlong_as_double(l_);                       \
            _Pragma("unroll")                                                 \
            for (int c = 0; c < 8; ++c) ffma2(PC[c], xb[j + c], w_);          \
        }                                                                     \
    } while (0)

    // r = 0,1: only pcA (pairs (w0,0), (w1,w0))
    LOADROW(0); ACC1P(pcA, 0, 0);
    LOADROW(1); ACC1P(pcA, 1, 0);

    // r = 2..21: pcA with (w[r],w[r-1]), pcB with (w[r-2],w[r-3])
    #pragma unroll 1
    for (int r = 2; r <= 21; ++r) {
        LOADROW(r);
        ACC2Q(r);
    }

    // r = 22,23: only pcB (hi pairs (w20,w19), (0,w20))
    LOADROW(22); ACC1P(pcB, 22, 8);
    LOADROW(23); ACC1P(pcB, 23, 8);

    // ---- unpack lanes, write 4 x 8 outputs ----
    const int oh = by * TH + rb;
    const int ow = bx * TW + wc;
    float* op = out + (long)bz * (HH * WW) + (long)oh * WW + ow;

    float r0[8], r1[8], r2[8], r3[8];
    #pragma unroll
    for (int c = 0; c < 8; ++c) {
        unpack2(r0[c], r1[c], pcA[c]);
        unpack2(r2[c], r3[c], pcB[c]);
    }
    #pragma unroll
    for (int v = 0; v < 2; ++v) {
        *reinterpret_cast<float4*>(op + 0*WW + 4*v) = make_float4(r0[4*v], r0[4*v+1], r0[4*v+2], r0[4*v+3]);
        *reinterpret_cast<float4*>(op + 1*WW + 4*v) = make_float4(r1[4*v], r1[4*v+1], r1[4*v+2], r1[4*v+3]);
        *reinterpret_cast<float4*>(op + 2*WW + 4*v) = make_float4(r2[4*v], r2[4*v+1], r2[4*v+2], r2[4*v+3]);
        *reinterpret_cast<float4*>(op + 3*WW + 4*v) = make_float4(r3[4*v], r3[4*v+1], r3[4*v+2], r3[4*v+3]);
    }

    #undef LOADROW
    #undef ACC2Q
    #undef ACC1P
}

extern "C" void kernel_launch(void* const* d_in, const int* in_sizes, int n_in,
                              void* d_out, int out_size)
{
    const float* in  = (const float*)d_in[0];   // (16,3,768,768)
    const float* ker = (const float*)d_in[1];   // (16,21,21)
    float* out = (float*)d_out;

    cudaFuncSetAttribute(blur_kernel,
                         cudaFuncAttributeMaxDynamicSharedMemorySize, SMEM_BYTES);

    dim3 grid(WW / TW, HH / TH, BB * CC);       // (6, 16, 48)
    blur_kernel<<<grid, NTHREADS, SMEM_BYTES>>>(in, ker, out);
}